// round 2
// baseline (speedup 1.0000x reference)
#include <cuda_runtime.h>

// Single-kernel deterministic reduction for 0.5 * sum((d1-d2)^2).
// Each of 1184 blocks (one full wave: 148 SMs x 8 blocks x 256 thr) writes a
// partial to a __device__ global, then the LAST block to finish (elected via an
// int atomic counter) sums all partials in fixed index order and writes out[0].
// Float summation order is fully fixed -> bitwise deterministic across replays.
// Counter is reset by the finisher so graph replays start clean.

#define GRID_BLOCKS 1184
#define BLOCK_THREADS 256

__device__ float g_partials[GRID_BLOCKS];
__device__ unsigned int g_counter = 0;

__global__ void __launch_bounds__(BLOCK_THREADS)
mse_fused_kernel(const float4* __restrict__ a,
                 const float4* __restrict__ b,
                 int n4,
                 float* __restrict__ out)
{
    float acc = 0.0f;
    const int stride = gridDim.x * blockDim.x;
    int i = blockIdx.x * blockDim.x + threadIdx.x;

    #pragma unroll 4
    for (; i < n4; i += stride) {
        float4 x = a[i];
        float4 y = b[i];
        float d0 = x.x - y.x;
        float d1 = x.y - y.y;
        float d2 = x.z - y.z;
        float d3 = x.w - y.w;
        acc = fmaf(d0, d0, acc);
        acc = fmaf(d1, d1, acc);
        acc = fmaf(d2, d2, acc);
        acc = fmaf(d3, d3, acc);
    }

    // Block reduce
    #pragma unroll
    for (int o = 16; o > 0; o >>= 1)
        acc += __shfl_down_sync(0xffffffffu, acc, o);

    __shared__ float smem[BLOCK_THREADS / 32];
    __shared__ bool is_last;
    const int lane = threadIdx.x & 31;
    const int wid  = threadIdx.x >> 5;
    if (lane == 0) smem[wid] = acc;
    __syncthreads();

    if (wid == 0) {
        acc = (lane < BLOCK_THREADS / 32) ? smem[lane] : 0.0f;
        #pragma unroll
        for (int o = 16; o > 0; o >>= 1)
            acc += __shfl_down_sync(0xffffffffu, acc, o);
        if (lane == 0) {
            g_partials[blockIdx.x] = acc;
            __threadfence();
            unsigned int prev = atomicAdd(&g_counter, 1u);
            is_last = (prev == GRID_BLOCKS - 1);
        }
    }
    __syncthreads();

    if (!is_last) return;

    // Finisher block: sum 1184 partials in fixed order (deterministic).
    __threadfence();
    float fin = 0.0f;
    for (int j = threadIdx.x; j < GRID_BLOCKS; j += BLOCK_THREADS)
        fin += g_partials[j];

    #pragma unroll
    for (int o = 16; o > 0; o >>= 1)
        fin += __shfl_down_sync(0xffffffffu, fin, o);

    if (lane == 0) smem[wid] = fin;
    __syncthreads();

    if (wid == 0) {
        fin = (lane < BLOCK_THREADS / 32) ? smem[lane] : 0.0f;
        #pragma unroll
        for (int o = 16; o > 0; o >>= 1)
            fin += __shfl_down_sync(0xffffffffu, fin, o);
        if (lane == 0) {
            out[0] = 0.5f * fin;
            g_counter = 0;   // reset for next graph replay
        }
    }
}

extern "C" void kernel_launch(void* const* d_in, const int* in_sizes, int n_in,
                              void* d_out, int out_size)
{
    const float* d1 = (const float*)d_in[0];
    const float* d2 = (const float*)d_in[1];
    float* out = (float*)d_out;

    const int n  = in_sizes[0];   // 40,000,000 (multiple of 4)
    const int n4 = n >> 2;

    mse_fused_kernel<<<GRID_BLOCKS, BLOCK_THREADS>>>(
        (const float4*)d1, (const float4*)d2, n4, out);
}

// round 3
// speedup vs baseline: 1.0730x; 1.0730x over previous
#include <cuda_runtime.h>

// Two-stage deterministic reduction for 0.5 * sum((d1-d2)^2).
// Stage 1: 1184 blocks (one full wave: 148 SMs x 8 x 256 thr), streaming
//          __ldcs float4 loads, one partial per block into a __device__ global.
// Stage 2: 128-thread block; vectorized float4 loads of the 1184 partials
//          (fixed summation order -> bitwise deterministic), writes out[0].

#define GRID_BLOCKS 1184          // multiple of 4 -> partials readable as float4
#define BLOCK_THREADS 256
#define FIN_THREADS 128

__device__ float g_partials[GRID_BLOCKS];

__global__ void __launch_bounds__(BLOCK_THREADS)
mse_partial_kernel(const float4* __restrict__ a,
                   const float4* __restrict__ b,
                   int n4)
{
    float acc = 0.0f;
    const int stride = gridDim.x * blockDim.x;
    int i = blockIdx.x * blockDim.x + threadIdx.x;

    #pragma unroll 4
    for (; i < n4; i += stride) {
        float4 x = __ldcs(a + i);   // streaming: read-once data, evict-first
        float4 y = __ldcs(b + i);
        float d0 = x.x - y.x;
        float d1 = x.y - y.y;
        float d2 = x.z - y.z;
        float d3 = x.w - y.w;
        acc = fmaf(d0, d0, acc);
        acc = fmaf(d1, d1, acc);
        acc = fmaf(d2, d2, acc);
        acc = fmaf(d3, d3, acc);
    }

    // Warp reduce
    #pragma unroll
    for (int o = 16; o > 0; o >>= 1)
        acc += __shfl_down_sync(0xffffffffu, acc, o);

    __shared__ float smem[BLOCK_THREADS / 32];
    const int lane = threadIdx.x & 31;
    const int wid  = threadIdx.x >> 5;
    if (lane == 0) smem[wid] = acc;
    __syncthreads();

    if (wid == 0) {
        acc = (lane < BLOCK_THREADS / 32) ? smem[lane] : 0.0f;
        #pragma unroll
        for (int o = 16; o > 0; o >>= 1)
            acc += __shfl_down_sync(0xffffffffu, acc, o);
        if (lane == 0) g_partials[blockIdx.x] = acc;
    }
}

__global__ void __launch_bounds__(FIN_THREADS)
mse_final_kernel(float* __restrict__ out, int n4_times4, int n,
                 const float* __restrict__ a_s, const float* __restrict__ b_s)
{
    // 1184 partials = 296 float4. 128 threads -> 2-3 vector loads each,
    // all independent (high MLP, one DRAM/L2 latency chain).
    const float4* p4 = (const float4*)g_partials;
    const int NV = GRID_BLOCKS / 4;   // 296

    float acc = 0.0f;
    #pragma unroll
    for (int j = threadIdx.x; j < NV; j += FIN_THREADS) {
        float4 v = p4[j];
        acc += (v.x + v.y) + (v.z + v.w);
    }

    // Scalar tail of the input (n not multiple of 4) — thread 0 only.
    if (threadIdx.x == 0) {
        for (int t = n4_times4; t < n; ++t) {
            float d = a_s[t] - b_s[t];
            acc = fmaf(d, d, acc);
        }
    }

    #pragma unroll
    for (int o = 16; o > 0; o >>= 1)
        acc += __shfl_down_sync(0xffffffffu, acc, o);

    __shared__ float smem[FIN_THREADS / 32];
    const int lane = threadIdx.x & 31;
    const int wid  = threadIdx.x >> 5;
    if (lane == 0) smem[wid] = acc;
    __syncthreads();

    if (threadIdx.x == 0) {
        float fin = (smem[0] + smem[1]) + (smem[2] + smem[3]);
        out[0] = 0.5f * fin;
    }
}

extern "C" void kernel_launch(void* const* d_in, const int* in_sizes, int n_in,
                              void* d_out, int out_size)
{
    const float* d1 = (const float*)d_in[0];
    const float* d2 = (const float*)d_in[1];
    float* out = (float*)d_out;

    const int n  = in_sizes[0];   // 40,000,000
    const int n4 = n >> 2;

    mse_partial_kernel<<<GRID_BLOCKS, BLOCK_THREADS>>>(
        (const float4*)d1, (const float4*)d2, n4);
    mse_final_kernel<<<1, FIN_THREADS>>>(out, n4 << 2, n, d1, d2);
}